// round 10
// baseline (speedup 1.0000x reference)
#include <cuda_runtime.h>
#include <math_constants.h>

#define IN_DIM   256
#define CODE_LEN 128
#define MEM_LEN  65536
#define NT       256
#define GRID_S   1184                 // 148 * 8 -> 64 warps/SM (full cap)
#define GRID_D   2048                 // 16384 warps -> exactly 1 quad (4 rows) per warp
#define NWARP_S  (GRID_S * NT / 32)   // 9472
#define NWARP_D  (GRID_D * NT / 32)   // 16384

#define N_MD  (MEM_LEN * IN_DIM)      // 16777216 floats
#define N_MEM (MEM_LEN * CODE_LEN)    //  8388608 floats
#define S_MD  ((N_MD  - 7) / 4 + 1)   // 4194303 aligned slots
#define S_MEM ((N_MEM - 7) / 4 + 1)   // 2097151 aligned slots

// Output layout (flattened tuple, all f32):
#define OUT_MEM_OFF 1LL
#define OUT_MD_OFF  (1LL + (long long)N_MEM)
#define OUT_IDX_OFF (OUT_MD_OFF + (long long)N_MD)

// Scratch (device globals; statically armed, re-armed by k_dist's final block)
__device__ float               g_colsum[IN_DIM];                  // zero-init
__device__ float               g_colsq[IN_DIM];                   // zero-init
__device__ __align__(16) float g_enc[CODE_LEN];
__device__ int                 g_minbits = 0x7f800000;            // +inf
__device__ unsigned long long  g_argmin  = 0xFFFFFFFFFFFFFFFFULL;
__device__ unsigned            g_ticket  = 0;
__device__ unsigned            g_sdone   = 0;                     // stats blocks done

#define FULL 0xFFFFFFFFu

// ---------------------------------------------------------------------------
// K1: mem_data [65536,256] — realigned copy (STG.128) + column sum/sumsq
//     + mem_idx copy/argmin + enc tail on blocks 0..127 (unchanged logic).
// ---------------------------------------------------------------------------
__global__ void __launch_bounds__(NT)
k_stats(const float* __restrict__ md_f, float* __restrict__ out_md,
        const int* __restrict__ idx, float* __restrict__ out_idx,
        const float* __restrict__ x, const float* __restrict__ W,
        const float* __restrict__ bias) {
    const float4* md4  = (const float4*)md_f;
    float4*       out4 = (float4*)(out_md + 3);        // 16B-aligned
    const int tid  = threadIdx.x;
    const int lane = tid & 31;
    const int wid  = tid >> 5;
    const int gw   = blockIdx.x * 8 + wid;
    const unsigned stride = NWARP_S * 64u;

    __shared__ float sW[IN_DIM];
    if (blockIdx.x < CODE_LEN) sW[tid] = W[blockIdx.x * IN_DIM + tid];

    float s0 = 0, s1 = 0, s2 = 0, s3 = 0;
    float q0 = 0, q1 = 0, q2 = 0, q3 = 0;
    unsigned wb0 = (unsigned)(gw >> 1) * 128u + (unsigned)(gw & 1) * 32u;

    for (unsigned wb = wb0; wb < S_MD; wb += stride) {
        unsigned k1 = wb + lane;
        unsigned k2 = k1 + 64u;
        bool ok1 = k1 < S_MD;
        bool ok2 = k2 < S_MD;
        float4 v1 = ok1 ? md4[k1 + 1] : make_float4(0.f, 0.f, 0.f, 0.f);
        float4 v2 = ok2 ? md4[k2 + 1] : make_float4(0.f, 0.f, 0.f, 0.f);
        float pw1 = __shfl_up_sync(FULL, v1.w, 1);
        float pw2 = __shfl_up_sync(FULL, v2.w, 1);
        if (lane == 0) {
            pw1 = md_f[4u * wb + 3u];
            if (wb + 64u < S_MD) pw2 = md_f[4u * (wb + 64u) + 3u];
        }
        if (ok1) out4[k1] = make_float4(pw1, v1.x, v1.y, v1.z);
        if (ok2) out4[k2] = make_float4(pw2, v2.x, v2.y, v2.z);
        s0 += v1.x + v2.x; q0 += v1.x * v1.x + v2.x * v2.x;
        s1 += v1.y + v2.y; q1 += v1.y * v1.y + v2.y * v2.y;
        s2 += v1.z + v2.z; q2 += v1.z * v1.z + v2.z * v2.z;
        s3 += v1.w + v2.w; q3 += v1.w * v1.w + v2.w * v2.w;
    }

    int col = (int)((4u * (wb0 + lane) + 4u) & 255u);

    __shared__ float sh_s[8][IN_DIM];
    __shared__ float sh_q[8][IN_DIM];
    #pragma unroll
    for (int j = 0; j < 8; j++) { sh_s[j][tid] = 0.f; sh_q[j][tid] = 0.f; }
    __syncthreads();
    sh_s[wid][col] = s0; sh_s[wid][col + 1] = s1; sh_s[wid][col + 2] = s2; sh_s[wid][col + 3] = s3;
    sh_q[wid][col] = q0; sh_q[wid][col + 1] = q1; sh_q[wid][col + 2] = q2; sh_q[wid][col + 3] = q3;
    __syncthreads();
    float ts = 0.f, tq = 0.f;
    #pragma unroll
    for (int j = 0; j < 8; j++) { ts += sh_s[j][tid]; tq += sh_q[j][tid]; }
    atomicAdd(&g_colsum[tid], ts);
    atomicAdd(&g_colsq[tid],  tq);

    // mem_idx copy + packed argmin (dense over blocks 0..255)
    int gtid = blockIdx.x * NT + tid;
    if (gtid < MEM_LEN) {
        int v = idx[gtid];
        out_idx[gtid] = (float)v;
        unsigned long long key =
            ((unsigned long long)(unsigned)(v ^ 0x80000000) << 32) | (unsigned long long)gtid;
        #pragma unroll
        for (int off = 16; off; off >>= 1) {
            unsigned long long o = __shfl_xor_sync(FULL, key, off);
            key = (o < key) ? o : key;
        }
        if (lane == 0) atomicMin(&g_argmin, key);
    }

    // Head/tail elements + stats for input elements 0..3
    if (blockIdx.x == 0 && tid == 0) {
        out_md[0] = md_f[0]; out_md[1] = md_f[1]; out_md[2] = md_f[2];
        out_md[N_MD - 1] = md_f[N_MD - 1];
        #pragma unroll
        for (int j = 0; j < 4; j++) {
            float v = md_f[j];
            atomicAdd(&g_colsum[j], v);
            atomicAdd(&g_colsq[j],  v * v);
        }
    }

    // Publish this block's contributions, then count it done.
    __threadfence();
    __syncthreads();
    if (tid == 0) atomicAdd(&g_sdone, 1u);

    // ---- enc tail: blocks 0..127 wait for all blocks, compute their row ----
    if (blockIdx.x < CODE_LEN) {
        if (tid == 0) {
            while (*(volatile unsigned*)&g_sdone < (unsigned)GRID_S) __nanosleep(32);
        }
        __syncthreads();
        __threadfence();   // acquire: see all g_colsum/g_colsq
        float mean = g_colsum[tid] * (1.0f / (float)MEM_LEN);
        float var  = (g_colsq[tid] - (float)MEM_LEN * mean * mean) * (1.0f / (float)(MEM_LEN - 1));
        float sd   = sqrtf(fmaxf(var, 0.0f));
        float nv   = (sd == 0.0f) ? 0.0f : (x[tid] - mean) / sd;
        float p    = nv * sW[tid];
        #pragma unroll
        for (int off = 16; off; off >>= 1) p += __shfl_xor_sync(FULL, p, off);
        __shared__ float red[8];
        if (lane == 0) red[wid] = p;
        __syncthreads();
        if (tid == 0) {
            float a = bias[blockIdx.x];
            #pragma unroll
            for (int i = 0; i < 8; i++) a += red[i];
            g_enc[blockIdx.x] = a;
        }
    }
}

// ---------------------------------------------------------------------------
// K2: memory [65536,128] — ONE quad (4 rows) per warp: group g=lane>>3 owns
//     row 4q+g, lane sub=lane&7 loads 4 float4s at column stride 8.
//     Row sum: 3 shfl_xor in-group; quad min: 2 shfl_xor across groups.
//     Realigned copy via store-index shift. Last block does the final.
// ---------------------------------------------------------------------------
__global__ void __launch_bounds__(NT)
k_dist(const float* __restrict__ mem_f, float* __restrict__ out_mem,
       const float* __restrict__ x, const int* __restrict__ count,
       float* __restrict__ out) {
    const float4* mem4 = (const float4*)mem_f;
    float4*       out4 = (float4*)(out_mem + 3);       // 16B-aligned
    const int tid  = threadIdx.x;
    const int lane = tid & 31;
    const int sub  = lane & 7;
    const int g    = lane >> 3;
    const int q    = (blockIdx.x * NT + tid) >> 5;     // quad index, 0..16383

    const float4* enc4 = (const float4*)g_enc;
    float4 e0 = enc4[sub];
    float4 e1 = enc4[sub + 8];
    float4 e2 = enc4[sub + 16];
    float4 e3 = enc4[sub + 24];

    unsigned base = (unsigned)(4 * q + g) * 32u + (unsigned)sub;
    float4 v0 = mem4[base];
    float4 v1 = mem4[base + 8u];
    float4 v2 = mem4[base + 16u];
    float4 v3 = mem4[base + 24u];

    float p = fabsf(v0.x - e0.x) + fabsf(v0.y - e0.y) + fabsf(v0.z - e0.z) + fabsf(v0.w - e0.w)
            + fabsf(v1.x - e1.x) + fabsf(v1.y - e1.y) + fabsf(v1.z - e1.z) + fabsf(v1.w - e1.w)
            + fabsf(v2.x - e2.x) + fabsf(v2.y - e2.y) + fabsf(v2.z - e2.z) + fabsf(v2.w - e2.w)
            + fabsf(v3.x - e3.x) + fabsf(v3.y - e3.y) + fabsf(v3.z - e3.z) + fabsf(v3.w - e3.w);

    // realigned copy: slot i-1 = {prev elem .w, my .xyz}
    float pw0 = __shfl_up_sync(FULL, v0.w, 1);
    float pw1 = __shfl_up_sync(FULL, v1.w, 1);
    float pw2 = __shfl_up_sync(FULL, v2.w, 1);
    float pw3 = __shfl_up_sync(FULL, v3.w, 1);
    if (sub == 0) {
        if (base > 0u) pw0 = mem_f[4u * base - 1u];
        pw1 = mem_f[4u * (base + 8u)  - 1u];
        pw2 = mem_f[4u * (base + 16u) - 1u];
        pw3 = mem_f[4u * (base + 24u) - 1u];
    }
    if (base != 0u) out4[base - 1u] = make_float4(pw0, v0.x, v0.y, v0.z);
    out4[base + 7u]  = make_float4(pw1, v1.x, v1.y, v1.z);
    out4[base + 15u] = make_float4(pw2, v2.x, v2.y, v2.z);
    out4[base + 23u] = make_float4(pw3, v3.x, v3.y, v3.z);

    // row sum within 8-lane group, then min across the 4 groups
    p += __shfl_xor_sync(FULL, p, 1);
    p += __shfl_xor_sync(FULL, p, 2);
    p += __shfl_xor_sync(FULL, p, 4);
    float m = fminf(p, __shfl_xor_sync(FULL, p, 8));
    m = fminf(m, __shfl_xor_sync(FULL, m, 16));
    if (lane == 0) atomicMin(&g_minbits, __float_as_int(m));

    if (blockIdx.x == 0 && tid == 0) {
        out_mem[0] = mem_f[0]; out_mem[1] = mem_f[1]; out_mem[2] = mem_f[2];
        out_mem[N_MEM - 1] = mem_f[N_MEM - 1];
    }

    // --- last-block final ---
    __threadfence();
    __syncthreads();
    __shared__ int s_last;
    if (tid == 0) s_last = (atomicAdd(&g_ticket, 1) == GRID_D - 1) ? 1 : 0;
    __syncthreads();
    if (s_last) {
        float loss = __int_as_float(atomicAdd(&g_minbits, 0));
        unsigned long long am = atomicAdd(&g_argmin, 0ULL);
        long long pos = (long long)(unsigned)(am & 0xFFFFFFFFULL);
        if (tid == 0) out[0] = loss;
        if (loss <= 1.0f) {
            if (tid < CODE_LEN) out[OUT_MEM_OFF + pos * CODE_LEN + tid] = g_enc[tid];
            out[OUT_MD_OFF + pos * IN_DIM + tid] = x[tid];
            if (tid == 0) out[OUT_IDX_OFF + pos] = (float)count[0];
        }
        __syncthreads();                 // done reading accumulators
        g_colsum[tid] = 0.0f;            // re-arm for next graph replay
        g_colsq[tid]  = 0.0f;
        if (tid == 0) {
            g_minbits = 0x7f800000;
            g_argmin  = 0xFFFFFFFFFFFFFFFFULL;
            g_ticket  = 0;
            g_sdone   = 0;
        }
    }
}

// ---------------------------------------------------------------------------
extern "C" void kernel_launch(void* const* d_in, const int* in_sizes, int n_in,
                              void* d_out, int out_size) {
    const float* x        = (const float*)d_in[0];
    const float* memory   = (const float*)d_in[1];
    const float* mem_data = (const float*)d_in[2];
    const int*   mem_idx  = (const int*)d_in[3];
    const float* W        = (const float*)d_in[4];
    const float* b        = (const float*)d_in[5];
    const int*   count    = (const int*)d_in[6];
    float* out = (float*)d_out;

    k_stats<<<GRID_S, NT>>>(mem_data, out + OUT_MD_OFF,
                            mem_idx, out + OUT_IDX_OFF, x, W, b);
    k_dist <<<GRID_D, NT>>>(memory, out + OUT_MEM_OFF, x, count, out);
}

// round 11
// speedup vs baseline: 1.0538x; 1.0538x over previous
#include <cuda_runtime.h>
#include <math_constants.h>

#define IN_DIM   256
#define CODE_LEN 128
#define MEM_LEN  65536
#define NT       256
#define GRID_S   888                  // 148 * 6
#define GRID_D   1024                 // 8192 warps -> 2 quads (8 rows) per warp
#define NWARP_S  (GRID_S * NT / 32)   // 7104
#define NWARP_D  (GRID_D * NT / 32)   // 8192

#define N_MD  (MEM_LEN * IN_DIM)      // 16777216 floats
#define N_MEM (MEM_LEN * CODE_LEN)    //  8388608 floats
#define S_MD  ((N_MD  - 7) / 4 + 1)   // 4194303 aligned slots
#define S_MEM ((N_MEM - 7) / 4 + 1)   // 2097151 aligned slots

// Output layout (flattened tuple, all f32):
#define OUT_MEM_OFF 1LL
#define OUT_MD_OFF  (1LL + (long long)N_MEM)
#define OUT_IDX_OFF (OUT_MD_OFF + (long long)N_MD)

// Scratch (device globals; statically armed, re-armed by k_dist's final block)
__device__ float               g_colsum[IN_DIM];                  // zero-init
__device__ float               g_colsq[IN_DIM];                   // zero-init
__device__ __align__(16) float g_enc[CODE_LEN];
__device__ int                 g_minbits = 0x7f800000;            // +inf
__device__ unsigned long long  g_argmin  = 0xFFFFFFFFFFFFFFFFULL;
__device__ unsigned            g_ticket  = 0;
__device__ unsigned            g_sdone   = 0;                     // stats blocks done

#define FULL 0xFFFFFFFFu

// ---------------------------------------------------------------------------
// K1: ALL streaming. (a) mem_data [65536,256]: realigned copy + col stats.
//     (b) memory [65536,128]: realigned copy — done LAST so its lines are the
//     freshest in L2 for k_dist's read pass. (c) mem_idx copy + argmin.
//     (d) enc tail on blocks 0..127 after a done-counter.
// ---------------------------------------------------------------------------
__global__ void __launch_bounds__(NT)
k_stats(const float* __restrict__ md_f, float* __restrict__ out_md,
        const float* __restrict__ mem_f, float* __restrict__ out_mem,
        const int* __restrict__ idx, float* __restrict__ out_idx,
        const float* __restrict__ x, const float* __restrict__ W,
        const float* __restrict__ bias) {
    const float4* md4   = (const float4*)md_f;
    const float4* mem4  = (const float4*)mem_f;
    float4*       out4  = (float4*)(out_md + 3);       // 16B-aligned
    float4*       out4m = (float4*)(out_mem + 3);      // 16B-aligned
    const int tid  = threadIdx.x;
    const int lane = tid & 31;
    const int wid  = tid >> 5;
    const int gw   = blockIdx.x * 8 + wid;
    const unsigned stride = NWARP_S * 64u;

    __shared__ float sW[IN_DIM];
    if (blockIdx.x < CODE_LEN) sW[tid] = W[blockIdx.x * IN_DIM + tid];

    // ---- (a) mem_data: stats + realigned copy (warp-pair tiling, MLP 2) ----
    float s0 = 0, s1 = 0, s2 = 0, s3 = 0;
    float q0 = 0, q1 = 0, q2 = 0, q3 = 0;
    unsigned wb0 = (unsigned)(gw >> 1) * 128u + (unsigned)(gw & 1) * 32u;

    for (unsigned wb = wb0; wb < S_MD; wb += stride) {
        unsigned k1 = wb + lane;
        unsigned k2 = k1 + 64u;
        bool ok1 = k1 < S_MD;
        bool ok2 = k2 < S_MD;
        float4 v1 = ok1 ? md4[k1 + 1] : make_float4(0.f, 0.f, 0.f, 0.f);
        float4 v2 = ok2 ? md4[k2 + 1] : make_float4(0.f, 0.f, 0.f, 0.f);
        float pw1 = __shfl_up_sync(FULL, v1.w, 1);
        float pw2 = __shfl_up_sync(FULL, v2.w, 1);
        if (lane == 0) {
            pw1 = md_f[4u * wb + 3u];
            if (wb + 64u < S_MD) pw2 = md_f[4u * (wb + 64u) + 3u];
        }
        if (ok1) out4[k1] = make_float4(pw1, v1.x, v1.y, v1.z);
        if (ok2) out4[k2] = make_float4(pw2, v2.x, v2.y, v2.z);
        s0 += v1.x + v2.x; q0 += v1.x * v1.x + v2.x * v2.x;
        s1 += v1.y + v2.y; q1 += v1.y * v1.y + v2.y * v2.y;
        s2 += v1.z + v2.z; q2 += v1.z * v1.z + v2.z * v2.z;
        s3 += v1.w + v2.w; q3 += v1.w * v1.w + v2.w * v2.w;
    }

    int col = (int)((4u * (wb0 + lane) + 4u) & 255u);

    __shared__ float sh_s[8][IN_DIM];
    __shared__ float sh_q[8][IN_DIM];
    #pragma unroll
    for (int j = 0; j < 8; j++) { sh_s[j][tid] = 0.f; sh_q[j][tid] = 0.f; }
    __syncthreads();
    sh_s[wid][col] = s0; sh_s[wid][col + 1] = s1; sh_s[wid][col + 2] = s2; sh_s[wid][col + 3] = s3;
    sh_q[wid][col] = q0; sh_q[wid][col + 1] = q1; sh_q[wid][col + 2] = q2; sh_q[wid][col + 3] = q3;
    __syncthreads();
    float ts = 0.f, tq = 0.f;
    #pragma unroll
    for (int j = 0; j < 8; j++) { ts += sh_s[j][tid]; tq += sh_q[j][tid]; }
    atomicAdd(&g_colsum[tid], ts);
    atomicAdd(&g_colsq[tid],  tq);

    // ---- (c) mem_idx copy + packed argmin (dense over blocks 0..255) ----
    int gtid = blockIdx.x * NT + tid;
    if (gtid < MEM_LEN) {
        int v = idx[gtid];
        out_idx[gtid] = (float)v;
        unsigned long long key =
            ((unsigned long long)(unsigned)(v ^ 0x80000000) << 32) | (unsigned long long)gtid;
        #pragma unroll
        for (int off = 16; off; off >>= 1) {
            unsigned long long o = __shfl_xor_sync(FULL, key, off);
            key = (o < key) ? o : key;
        }
        if (lane == 0) atomicMin(&g_argmin, key);
    }

    // ---- (b) memory: realigned copy, LAST (freshest in L2), MLP 2 ----
    {
        const unsigned mstride = NWARP_S * 64u;
        for (unsigned wb = (unsigned)gw * 32u; wb < S_MEM; wb += mstride) {
            unsigned k1 = wb + lane;
            unsigned wb2 = wb + NWARP_S * 32u;
            unsigned k2 = wb2 + lane;
            bool ok1 = k1 < S_MEM;
            bool ok2 = k2 < S_MEM;
            float4 v1 = ok1 ? mem4[k1 + 1] : make_float4(0.f, 0.f, 0.f, 0.f);
            float4 v2 = ok2 ? mem4[k2 + 1] : make_float4(0.f, 0.f, 0.f, 0.f);
            float pw1 = __shfl_up_sync(FULL, v1.w, 1);
            float pw2 = __shfl_up_sync(FULL, v2.w, 1);
            if (lane == 0) {
                pw1 = mem_f[4u * wb + 3u];
                if (wb2 < S_MEM) pw2 = mem_f[4u * wb2 + 3u];
            }
            if (ok1) out4m[k1] = make_float4(pw1, v1.x, v1.y, v1.z);
            if (ok2) out4m[k2] = make_float4(pw2, v2.x, v2.y, v2.z);
        }
    }

    // Head/tail elements + stats for input elements 0..3
    if (blockIdx.x == 0 && tid == 0) {
        out_md[0] = md_f[0]; out_md[1] = md_f[1]; out_md[2] = md_f[2];
        out_md[N_MD - 1] = md_f[N_MD - 1];
        out_mem[0] = mem_f[0]; out_mem[1] = mem_f[1]; out_mem[2] = mem_f[2];
        out_mem[N_MEM - 1] = mem_f[N_MEM - 1];
        #pragma unroll
        for (int j = 0; j < 4; j++) {
            float v = md_f[j];
            atomicAdd(&g_colsum[j], v);
            atomicAdd(&g_colsq[j],  v * v);
        }
    }

    // Publish contributions, count this block done.
    __threadfence();
    __syncthreads();
    if (tid == 0) atomicAdd(&g_sdone, 1u);

    // ---- (d) enc tail: blocks 0..127 wait for all blocks, compute row ----
    if (blockIdx.x < CODE_LEN) {
        if (tid == 0) {
            while (*(volatile unsigned*)&g_sdone < (unsigned)GRID_S) __nanosleep(32);
        }
        __syncthreads();
        __threadfence();   // acquire
        float mean = g_colsum[tid] * (1.0f / (float)MEM_LEN);
        float var  = (g_colsq[tid] - (float)MEM_LEN * mean * mean) * (1.0f / (float)(MEM_LEN - 1));
        float sd   = sqrtf(fmaxf(var, 0.0f));
        float nv   = (sd == 0.0f) ? 0.0f : (x[tid] - mean) / sd;
        float p    = nv * sW[tid];
        #pragma unroll
        for (int off = 16; off; off >>= 1) p += __shfl_xor_sync(FULL, p, off);
        __shared__ float red[8];
        if (lane == 0) red[wid] = p;
        __syncthreads();
        if (tid == 0) {
            float a = bias[blockIdx.x];
            #pragma unroll
            for (int i = 0; i < 8; i++) a += red[i];
            g_enc[blockIdx.x] = a;
        }
    }
}

// ---------------------------------------------------------------------------
// K2: PURE READ + REDUCE over memory [65536,128] (copy already done in K1 —
//     reads should be largely L2-hits). Quad-per-warp layout, 2 quads/warp.
//     Last block writes loss + conditional scatter and re-arms globals.
// ---------------------------------------------------------------------------
__global__ void __launch_bounds__(NT)
k_dist(const float* __restrict__ mem_f,
       const float* __restrict__ x, const int* __restrict__ count,
       float* __restrict__ out) {
    const float4* mem4 = (const float4*)mem_f;
    const int tid  = threadIdx.x;
    const int lane = tid & 31;
    const int sub  = lane & 7;
    const int g    = lane >> 3;
    const int warp = (blockIdx.x * NT + tid) >> 5;     // 0..8191

    const float4* enc4 = (const float4*)g_enc;
    float4 e0 = enc4[sub];
    float4 e1 = enc4[sub + 8];
    float4 e2 = enc4[sub + 16];
    float4 e3 = enc4[sub + 24];

    float best = CUDART_INF_F;

    #pragma unroll
    for (int h = 0; h < 2; h++) {
        int q = warp + h * NWARP_D;                    // quad index, < 16384
        unsigned base = (unsigned)(4 * q + g) * 32u + (unsigned)sub;
        float4 v0 = mem4[base];
        float4 v1 = mem4[base + 8u];
        float4 v2 = mem4[base + 16u];
        float4 v3 = mem4[base + 24u];

        float p = fabsf(v0.x - e0.x) + fabsf(v0.y - e0.y) + fabsf(v0.z - e0.z) + fabsf(v0.w - e0.w)
                + fabsf(v1.x - e1.x) + fabsf(v1.y - e1.y) + fabsf(v1.z - e1.z) + fabsf(v1.w - e1.w)
                + fabsf(v2.x - e2.x) + fabsf(v2.y - e2.y) + fabsf(v2.z - e2.z) + fabsf(v2.w - e2.w)
                + fabsf(v3.x - e3.x) + fabsf(v3.y - e3.y) + fabsf(v3.z - e3.z) + fabsf(v3.w - e3.w);

        p += __shfl_xor_sync(FULL, p, 1);
        p += __shfl_xor_sync(FULL, p, 2);
        p += __shfl_xor_sync(FULL, p, 4);
        float m = fminf(p, __shfl_xor_sync(FULL, p, 8));
        m = fminf(m, __shfl_xor_sync(FULL, m, 16));
        best = fminf(best, m);
    }
    if (lane == 0) atomicMin(&g_minbits, __float_as_int(best));

    // --- last-block final ---
    __threadfence();
    __syncthreads();
    __shared__ int s_last;
    if (tid == 0) s_last = (atomicAdd(&g_ticket, 1) == GRID_D - 1) ? 1 : 0;
    __syncthreads();
    if (s_last) {
        float loss = __int_as_float(atomicAdd(&g_minbits, 0));
        unsigned long long am = atomicAdd(&g_argmin, 0ULL);
        long long pos = (long long)(unsigned)(am & 0xFFFFFFFFULL);
        if (tid == 0) out[0] = loss;
        if (loss <= 1.0f) {
            if (tid < CODE_LEN) out[OUT_MEM_OFF + pos * CODE_LEN + tid] = g_enc[tid];
            out[OUT_MD_OFF + pos * IN_DIM + tid] = x[tid];
            if (tid == 0) out[OUT_IDX_OFF + pos] = (float)count[0];
        }
        __syncthreads();                 // done reading accumulators
        g_colsum[tid] = 0.0f;            // re-arm for next graph replay
        g_colsq[tid]  = 0.0f;
        if (tid == 0) {
            g_minbits = 0x7f800000;
            g_argmin  = 0xFFFFFFFFFFFFFFFFULL;
            g_ticket  = 0;
            g_sdone   = 0;
        }
    }
}

// ---------------------------------------------------------------------------
extern "C" void kernel_launch(void* const* d_in, const int* in_sizes, int n_in,
                              void* d_out, int out_size) {
    const float* x        = (const float*)d_in[0];
    const float* memory   = (const float*)d_in[1];
    const float* mem_data = (const float*)d_in[2];
    const int*   mem_idx  = (const int*)d_in[3];
    const float* W        = (const float*)d_in[4];
    const float* b        = (const float*)d_in[5];
    const int*   count    = (const int*)d_in[6];
    float* out = (float*)d_out;

    k_stats<<<GRID_S, NT>>>(mem_data, out + OUT_MD_OFF,
                            memory,   out + OUT_MEM_OFF,
                            mem_idx,  out + OUT_IDX_OFF, x, W, b);
    k_dist <<<GRID_D, NT>>>(memory, x, count, out);
}

// round 12
// speedup vs baseline: 1.1238x; 1.0664x over previous
#include <cuda_runtime.h>
#include <math_constants.h>

#define IN_DIM   256
#define CODE_LEN 128
#define MEM_LEN  65536
#define NT       256
#define GRID     888                  // 148 * 6 — one co-resident wave
#define B_STATS  592                  // 2/3: mem_data (128 MB)
#define B_COPY   (GRID - B_STATS)     // 1/3: memory copy (64 MB)
#define NWARP_ST (B_STATS * 8)        // 4736
#define NWARP_CP (B_COPY * 8)         // 2368
#define NWARP_ALL (GRID * 8)          // 7104
#define NQUAD    (MEM_LEN / 4)        // 16384

#define N_MD  (MEM_LEN * IN_DIM)      // 16777216 floats
#define N_MEM (MEM_LEN * CODE_LEN)    //  8388608 floats
#define S_MD  ((N_MD  - 7) / 4 + 1)   // 4194303 aligned slots
#define S_MEM ((N_MEM - 7) / 4 + 1)   // 2097151 aligned slots

// Output layout (flattened tuple, all f32):
#define OUT_MEM_OFF 1LL
#define OUT_MD_OFF  (1LL + (long long)N_MEM)
#define OUT_IDX_OFF (OUT_MD_OFF + (long long)N_MD)

// Scratch (device globals; statically armed, re-armed by the final block)
__device__ float               g_colsum[IN_DIM];                  // zero-init
__device__ float               g_colsq[IN_DIM];                   // zero-init
__device__ __align__(16) float g_enc[CODE_LEN];
__device__ int                 g_minbits = 0x7f800000;            // +inf
__device__ unsigned long long  g_argmin  = 0xFFFFFFFFFFFFFFFFULL;
__device__ unsigned            g_ticket  = 0;
__device__ unsigned            g_sdone   = 0;                     // stats blocks done
__device__ unsigned            g_encdone = 0;                     // enc rows done

#define FULL 0xFFFFFFFFu

__global__ void __launch_bounds__(NT, 6)
fused(const float* __restrict__ md_f,  float* __restrict__ out_md,
      const float* __restrict__ mem_f, float* __restrict__ out_mem,
      const int* __restrict__ idx,     float* __restrict__ out_idx,
      const float* __restrict__ x,     const float* __restrict__ W,
      const float* __restrict__ bias,  const int* __restrict__ count,
      float* __restrict__ out) {
    const float4* md4   = (const float4*)md_f;
    const float4* mem4  = (const float4*)mem_f;
    float4*       o4md  = (float4*)(out_md + 3);       // 16B-aligned
    float4*       o4mem = (float4*)(out_mem + 3);      // 16B-aligned
    const int tid  = threadIdx.x;
    const int lane = tid & 31;
    const int wid  = tid >> 5;
    const bool is_stats = blockIdx.x < B_STATS;

    __shared__ float sW[IN_DIM];
    if (blockIdx.x < CODE_LEN) sW[tid] = W[blockIdx.x * IN_DIM + tid];

    if (is_stats) {
        // ================= mem_data: stats + realigned copy ================
        const int gw = blockIdx.x * 8 + wid;           // 0..4735
        const unsigned stride = NWARP_ST * 64u;
        float s0 = 0, s1 = 0, s2 = 0, s3 = 0;
        float q0 = 0, q1 = 0, q2 = 0, q3 = 0;
        unsigned wb0 = (unsigned)(gw >> 1) * 128u + (unsigned)(gw & 1) * 32u;

        for (unsigned wb = wb0; wb < S_MD; wb += stride) {
            unsigned k1 = wb + lane;
            unsigned k2 = k1 + 64u;
            bool ok1 = k1 < S_MD;
            bool ok2 = k2 < S_MD;
            float4 v1 = ok1 ? md4[k1 + 1] : make_float4(0.f, 0.f, 0.f, 0.f);
            float4 v2 = ok2 ? md4[k2 + 1] : make_float4(0.f, 0.f, 0.f, 0.f);
            float pw1 = __shfl_up_sync(FULL, v1.w, 1);
            float pw2 = __shfl_up_sync(FULL, v2.w, 1);
            if (lane == 0) {
                pw1 = md_f[4u * wb + 3u];
                if (wb + 64u < S_MD) pw2 = md_f[4u * (wb + 64u) + 3u];
            }
            if (ok1) o4md[k1] = make_float4(pw1, v1.x, v1.y, v1.z);
            if (ok2) o4md[k2] = make_float4(pw2, v2.x, v2.y, v2.z);
            s0 += v1.x + v2.x; q0 += v1.x * v1.x + v2.x * v2.x;
            s1 += v1.y + v2.y; q1 += v1.y * v1.y + v2.y * v2.y;
            s2 += v1.z + v2.z; q2 += v1.z * v1.z + v2.z * v2.z;
            s3 += v1.w + v2.w; q3 += v1.w * v1.w + v2.w * v2.w;
        }

        int col = (int)((4u * (wb0 + lane) + 4u) & 255u);
        __shared__ float sh_s[8][IN_DIM];
        __shared__ float sh_q[8][IN_DIM];
        #pragma unroll
        for (int j = 0; j < 8; j++) { sh_s[j][tid] = 0.f; sh_q[j][tid] = 0.f; }
        __syncthreads();
        sh_s[wid][col] = s0; sh_s[wid][col + 1] = s1; sh_s[wid][col + 2] = s2; sh_s[wid][col + 3] = s3;
        sh_q[wid][col] = q0; sh_q[wid][col + 1] = q1; sh_q[wid][col + 2] = q2; sh_q[wid][col + 3] = q3;
        __syncthreads();
        float ts = 0.f, tq = 0.f;
        #pragma unroll
        for (int j = 0; j < 8; j++) { ts += sh_s[j][tid]; tq += sh_q[j][tid]; }
        atomicAdd(&g_colsum[tid], ts);
        atomicAdd(&g_colsq[tid],  tq);

        // mem_idx copy + packed argmin (blocks 0..255 dense)
        int gtid = blockIdx.x * NT + tid;
        if (gtid < MEM_LEN) {
            int v = idx[gtid];
            out_idx[gtid] = (float)v;
            unsigned long long key =
                ((unsigned long long)(unsigned)(v ^ 0x80000000) << 32) | (unsigned long long)gtid;
            #pragma unroll
            for (int off = 16; off; off >>= 1) {
                unsigned long long o = __shfl_xor_sync(FULL, key, off);
                key = (o < key) ? o : key;
            }
            if (lane == 0) atomicMin(&g_argmin, key);
        }

        // Head/tail elements + stats for input elements 0..3
        if (blockIdx.x == 0 && tid == 0) {
            out_md[0] = md_f[0]; out_md[1] = md_f[1]; out_md[2] = md_f[2];
            out_md[N_MD - 1] = md_f[N_MD - 1];
            out_mem[0] = mem_f[0]; out_mem[1] = mem_f[1]; out_mem[2] = mem_f[2];
            out_mem[N_MEM - 1] = mem_f[N_MEM - 1];
            #pragma unroll
            for (int j = 0; j < 4; j++) {
                float v = md_f[j];
                atomicAdd(&g_colsum[j], v);
                atomicAdd(&g_colsq[j],  v * v);
            }
        }

        __threadfence();
        __syncthreads();
        if (tid == 0) atomicAdd(&g_sdone, 1u);

        // enc tail on blocks 0..127
        if (blockIdx.x < CODE_LEN) {
            if (tid == 0) {
                while (*(volatile unsigned*)&g_sdone < (unsigned)B_STATS) __nanosleep(32);
            }
            __syncthreads();
            __threadfence();   // acquire
            float mean = g_colsum[tid] * (1.0f / (float)MEM_LEN);
            float var  = (g_colsq[tid] - (float)MEM_LEN * mean * mean) * (1.0f / (float)(MEM_LEN - 1));
            float sd   = sqrtf(fmaxf(var, 0.0f));
            float nv   = (sd == 0.0f) ? 0.0f : (x[tid] - mean) / sd;
            float p    = nv * sW[tid];
            #pragma unroll
            for (int off = 16; off; off >>= 1) p += __shfl_xor_sync(FULL, p, off);
            __shared__ float red[8];
            if (lane == 0) red[wid] = p;
            __syncthreads();
            if (tid == 0) {
                float a = bias[blockIdx.x];
                #pragma unroll
                for (int i = 0; i < 8; i++) a += red[i];
                g_enc[blockIdx.x] = a;
                __threadfence();
                atomicAdd(&g_encdone, 1u);
            }
        }
    } else {
        // ================= memory: realigned copy (concurrent) =============
        const int gw2 = (blockIdx.x - B_STATS) * 8 + wid;   // 0..2367
        const unsigned stride = NWARP_CP * 64u;
        for (unsigned wb = (unsigned)gw2 * 32u; wb < S_MEM; wb += stride) {
            unsigned k1 = wb + lane;
            unsigned wb2 = wb + NWARP_CP * 32u;
            unsigned k2 = wb2 + lane;
            bool ok1 = k1 < S_MEM;
            bool ok2 = k2 < S_MEM;
            float4 v1 = ok1 ? mem4[k1 + 1] : make_float4(0.f, 0.f, 0.f, 0.f);
            float4 v2 = ok2 ? mem4[k2 + 1] : make_float4(0.f, 0.f, 0.f, 0.f);
            float pw1 = __shfl_up_sync(FULL, v1.w, 1);
            float pw2 = __shfl_up_sync(FULL, v2.w, 1);
            if (lane == 0) {
                pw1 = mem_f[4u * wb + 3u];
                if (wb2 < S_MEM) pw2 = mem_f[4u * wb2 + 3u];
            }
            if (ok1) o4mem[k1] = make_float4(pw1, v1.x, v1.y, v1.z);
            if (ok2) o4mem[k2] = make_float4(pw2, v2.x, v2.y, v2.z);
        }
    }

    // =================== everyone: wait for enc, then dist =================
    if (tid == 0) {
        while (*(volatile unsigned*)&g_encdone < (unsigned)CODE_LEN) __nanosleep(32);
    }
    __syncthreads();
    __threadfence();   // acquire g_enc

    {
        const int sub = lane & 7;
        const int g   = lane >> 3;
        const int w   = blockIdx.x * 8 + wid;          // 0..7103
        const float4* enc4 = (const float4*)g_enc;
        float4 e0 = enc4[sub];
        float4 e1 = enc4[sub + 8];
        float4 e2 = enc4[sub + 16];
        float4 e3 = enc4[sub + 24];

        float best = CUDART_INF_F;
        for (int q = w; q < NQUAD; q += NWARP_ALL) {
            unsigned base = (unsigned)(4 * q + g) * 32u + (unsigned)sub;
            float4 v0 = mem4[base];
            float4 v1 = mem4[base + 8u];
            float4 v2 = mem4[base + 16u];
            float4 v3 = mem4[base + 24u];
            float p = fabsf(v0.x - e0.x) + fabsf(v0.y - e0.y) + fabsf(v0.z - e0.z) + fabsf(v0.w - e0.w)
                    + fabsf(v1.x - e1.x) + fabsf(v1.y - e1.y) + fabsf(v1.z - e1.z) + fabsf(v1.w - e1.w)
                    + fabsf(v2.x - e2.x) + fabsf(v2.y - e2.y) + fabsf(v2.z - e2.z) + fabsf(v2.w - e2.w)
                    + fabsf(v3.x - e3.x) + fabsf(v3.y - e3.y) + fabsf(v3.z - e3.z) + fabsf(v3.w - e3.w);
            p += __shfl_xor_sync(FULL, p, 1);
            p += __shfl_xor_sync(FULL, p, 2);
            p += __shfl_xor_sync(FULL, p, 4);
            float m = fminf(p, __shfl_xor_sync(FULL, p, 8));
            m = fminf(m, __shfl_xor_sync(FULL, m, 16));
            best = fminf(best, m);
        }
        // block-level min staging: ONE global atomic per block
        __shared__ float smin[8];
        if (lane == 0) smin[wid] = best;
        __syncthreads();
        if (tid == 0) {
            float mm = smin[0];
            #pragma unroll
            for (int j = 1; j < 8; j++) mm = fminf(mm, smin[j]);
            atomicMin(&g_minbits, __float_as_int(mm));
        }
    }

    // =================== last-block final + re-arm =========================
    __threadfence();
    __syncthreads();
    __shared__ int s_last;
    if (tid == 0) s_last = (atomicAdd(&g_ticket, 1) == GRID - 1) ? 1 : 0;
    __syncthreads();
    if (s_last) {
        float loss = __int_as_float(atomicAdd(&g_minbits, 0));
        unsigned long long am = atomicAdd(&g_argmin, 0ULL);
        long long pos = (long long)(unsigned)(am & 0xFFFFFFFFULL);
        if (tid == 0) out[0] = loss;
        if (loss <= 1.0f) {
            if (tid < CODE_LEN) out[OUT_MEM_OFF + pos * CODE_LEN + tid] = g_enc[tid];
            out[OUT_MD_OFF + pos * IN_DIM + tid] = x[tid];
            if (tid == 0) out[OUT_IDX_OFF + pos] = (float)count[0];
        }
        __syncthreads();                 // done reading accumulators
        g_colsum[tid] = 0.0f;            // re-arm for next graph replay
        g_colsq[tid]  = 0.0f;
        if (tid == 0) {
            g_minbits = 0x7f800000;
            g_argmin  = 0xFFFFFFFFFFFFFFFFULL;
            g_ticket  = 0;
            g_sdone   = 0;
            g_encdone = 0;
        }
    }
}

// ---------------------------------------------------------------------------
extern "C" void kernel_launch(void* const* d_in, const int* in_sizes, int n_in,
                              void* d_out, int out_size) {
    const float* x        = (const float*)d_in[0];
    const float* memory   = (const float*)d_in[1];
    const float* mem_data = (const float*)d_in[2];
    const int*   mem_idx  = (const int*)d_in[3];
    const float* W        = (const float*)d_in[4];
    const float* b        = (const float*)d_in[5];
    const int*   count    = (const int*)d_in[6];
    float* out = (float*)d_out;

    fused<<<GRID, NT>>>(mem_data, out + OUT_MD_OFF,
                        memory,   out + OUT_MEM_OFF,
                        mem_idx,  out + OUT_IDX_OFF,
                        x, W, b, count, out);
}

// round 13
// speedup vs baseline: 1.1659x; 1.0375x over previous
#include <cuda_runtime.h>
#include <math_constants.h>

#define IN_DIM   256
#define CODE_LEN 128
#define MEM_LEN  65536
#define NT       256
#define GRID     888                  // 148 * 6 — one co-resident wave
#define B_STATS  592                  // 2/3: mem_data (134 MB traffic)
#define B_COPY   (GRID - B_STATS)     // 1/3: memory copy (67 MB traffic)
#define NWARP_ST (B_STATS * 8)        // 4736
#define NWARP_CP (B_COPY * 8)         // 2368
#define NWARP_ALL (GRID * 8)          // 7104
#define NQUAD    (MEM_LEN / 4)        // 16384

#define N_MD  (MEM_LEN * IN_DIM)      // 16777216 floats
#define N_MEM (MEM_LEN * CODE_LEN)    //  8388608 floats
#define S_MD  ((N_MD  - 7) / 4 + 1)   // 4194303 aligned slots
#define S_MEM ((N_MEM - 7) / 4 + 1)   // 2097151 aligned slots
#define MEM_LINES (N_MEM * 4 / 256)   // 131072 x 256B lines

// Output layout (flattened tuple, all f32):
#define OUT_MEM_OFF 1LL
#define OUT_MD_OFF  (1LL + (long long)N_MEM)
#define OUT_IDX_OFF (OUT_MD_OFF + (long long)N_MD)

// Scratch (device globals; statically armed, re-armed by the final block)
__device__ float               g_colsum[IN_DIM];                  // zero-init
__device__ float               g_colsq[IN_DIM];                   // zero-init
__device__ __align__(16) float g_enc[CODE_LEN];
__device__ int                 g_minbits = 0x7f800000;            // +inf
__device__ unsigned long long  g_argmin  = 0xFFFFFFFFFFFFFFFFULL;
__device__ unsigned            g_ticket  = 0;
__device__ unsigned            g_sdone   = 0;                     // stats blocks done
__device__ unsigned            g_encdone = 0;                     // enc rows done

#define FULL 0xFFFFFFFFu

__device__ __forceinline__ void prefetch_l2(const void* p) {
    asm volatile("prefetch.global.L2 [%0];" :: "l"(p));
}

__global__ void __launch_bounds__(NT, 6)
fused(const float* __restrict__ md_f,  float* __restrict__ out_md,
      const float* __restrict__ mem_f, float* __restrict__ out_mem,
      const int* __restrict__ idx,     float* __restrict__ out_idx,
      const float* __restrict__ x,     const float* __restrict__ W,
      const float* __restrict__ bias,  const int* __restrict__ count,
      float* __restrict__ out) {
    const float4* md4   = (const float4*)md_f;
    const float4* mem4  = (const float4*)mem_f;
    float4*       o4md  = (float4*)(out_md + 3);       // 16B-aligned
    float4*       o4mem = (float4*)(out_mem + 3);      // 16B-aligned
    const int tid  = threadIdx.x;
    const int lane = tid & 31;
    const int wid  = tid >> 5;
    const bool is_stats = blockIdx.x < B_STATS;

    __shared__ float sW[IN_DIM];
    if (blockIdx.x < CODE_LEN) sW[tid] = W[blockIdx.x * IN_DIM + tid];

    if (is_stats) {
        // ===== mem_data: stats + realigned copy (evict-first both ways) ====
        const int gw = blockIdx.x * 8 + wid;           // 0..4735
        const unsigned stride = NWARP_ST * 64u;
        float s0 = 0, s1 = 0, s2 = 0, s3 = 0;
        float q0 = 0, q1 = 0, q2 = 0, q3 = 0;
        unsigned wb0 = (unsigned)(gw >> 1) * 128u + (unsigned)(gw & 1) * 32u;

        for (unsigned wb = wb0; wb < S_MD; wb += stride) {
            unsigned k1 = wb + lane;
            unsigned k2 = k1 + 64u;
            bool ok1 = k1 < S_MD;
            bool ok2 = k2 < S_MD;
            float4 v1 = ok1 ? __ldcs(md4 + k1 + 1) : make_float4(0.f, 0.f, 0.f, 0.f);
            float4 v2 = ok2 ? __ldcs(md4 + k2 + 1) : make_float4(0.f, 0.f, 0.f, 0.f);
            float pw1 = __shfl_up_sync(FULL, v1.w, 1);
            float pw2 = __shfl_up_sync(FULL, v2.w, 1);
            if (lane == 0) {
                pw1 = md_f[4u * wb + 3u];
                if (wb + 64u < S_MD) pw2 = md_f[4u * (wb + 64u) + 3u];
            }
            if (ok1) __stcs(o4md + k1, make_float4(pw1, v1.x, v1.y, v1.z));
            if (ok2) __stcs(o4md + k2, make_float4(pw2, v2.x, v2.y, v2.z));
            s0 += v1.x + v2.x; q0 += v1.x * v1.x + v2.x * v2.x;
            s1 += v1.y + v2.y; q1 += v1.y * v1.y + v2.y * v2.y;
            s2 += v1.z + v2.z; q2 += v1.z * v1.z + v2.z * v2.z;
            s3 += v1.w + v2.w; q3 += v1.w * v1.w + v2.w * v2.w;
        }

        int col = (int)((4u * (wb0 + lane) + 4u) & 255u);
        __shared__ float sh_s[8][IN_DIM];
        __shared__ float sh_q[8][IN_DIM];
        #pragma unroll
        for (int j = 0; j < 8; j++) { sh_s[j][tid] = 0.f; sh_q[j][tid] = 0.f; }
        __syncthreads();
        sh_s[wid][col] = s0; sh_s[wid][col + 1] = s1; sh_s[wid][col + 2] = s2; sh_s[wid][col + 3] = s3;
        sh_q[wid][col] = q0; sh_q[wid][col + 1] = q1; sh_q[wid][col + 2] = q2; sh_q[wid][col + 3] = q3;
        __syncthreads();
        float ts = 0.f, tq = 0.f;
        #pragma unroll
        for (int j = 0; j < 8; j++) { ts += sh_s[j][tid]; tq += sh_q[j][tid]; }
        atomicAdd(&g_colsum[tid], ts);
        atomicAdd(&g_colsq[tid],  tq);

        // mem_idx copy + packed argmin (blocks 0..255 dense)
        int gtid = blockIdx.x * NT + tid;
        if (gtid < MEM_LEN) {
            int v = idx[gtid];
            out_idx[gtid] = (float)v;
            unsigned long long key =
                ((unsigned long long)(unsigned)(v ^ 0x80000000) << 32) | (unsigned long long)gtid;
            #pragma unroll
            for (int off = 16; off; off >>= 1) {
                unsigned long long o = __shfl_xor_sync(FULL, key, off);
                key = (o < key) ? o : key;
            }
            if (lane == 0) atomicMin(&g_argmin, key);
        }

        // Head/tail elements + stats for input elements 0..3
        if (blockIdx.x == 0 && tid == 0) {
            out_md[0] = md_f[0]; out_md[1] = md_f[1]; out_md[2] = md_f[2];
            out_md[N_MD - 1] = md_f[N_MD - 1];
            out_mem[0] = mem_f[0]; out_mem[1] = mem_f[1]; out_mem[2] = mem_f[2];
            out_mem[N_MEM - 1] = mem_f[N_MEM - 1];
            #pragma unroll
            for (int j = 0; j < 4; j++) {
                float v = md_f[j];
                atomicAdd(&g_colsum[j], v);
                atomicAdd(&g_colsq[j],  v * v);
            }
        }

        __threadfence();
        __syncthreads();
        if (tid == 0) atomicAdd(&g_sdone, 1u);

        // enc tail on blocks 0..127
        if (blockIdx.x < CODE_LEN) {
            if (tid == 0) {
                while (*(volatile unsigned*)&g_sdone < (unsigned)B_STATS) __nanosleep(32);
            }
            __syncthreads();
            __threadfence();   // acquire
            float mean = g_colsum[tid] * (1.0f / (float)MEM_LEN);
            float var  = (g_colsq[tid] - (float)MEM_LEN * mean * mean) * (1.0f / (float)(MEM_LEN - 1));
            float sd   = sqrtf(fmaxf(var, 0.0f));
            float nv   = (sd == 0.0f) ? 0.0f : (x[tid] - mean) / sd;
            float p    = nv * sW[tid];
            #pragma unroll
            for (int off = 16; off; off >>= 1) p += __shfl_xor_sync(FULL, p, off);
            __shared__ float red[8];
            if (lane == 0) red[wid] = p;
            __syncthreads();
            if (tid == 0) {
                float a = bias[blockIdx.x];
                #pragma unroll
                for (int i = 0; i < 8; i++) a += red[i];
                g_enc[blockIdx.x] = a;
                __threadfence();
                atomicAdd(&g_encdone, 1u);
            }
        }
    } else {
        // ===== memory: realigned copy (reads default/L2-resident, stores cs)
        const int gw2 = (blockIdx.x - B_STATS) * 8 + wid;   // 0..2367
        const unsigned stride = NWARP_CP * 64u;
        for (unsigned wb = (unsigned)gw2 * 32u; wb < S_MEM; wb += stride) {
            unsigned k1 = wb + lane;
            unsigned wb2 = wb + NWARP_CP * 32u;
            unsigned k2 = wb2 + lane;
            bool ok1 = k1 < S_MEM;
            bool ok2 = k2 < S_MEM;
            float4 v1 = ok1 ? mem4[k1 + 1] : make_float4(0.f, 0.f, 0.f, 0.f);
            float4 v2 = ok2 ? mem4[k2 + 1] : make_float4(0.f, 0.f, 0.f, 0.f);
            float pw1 = __shfl_up_sync(FULL, v1.w, 1);
            float pw2 = __shfl_up_sync(FULL, v2.w, 1);
            if (lane == 0) {
                pw1 = mem_f[4u * wb + 3u];
                if (wb2 < S_MEM) pw2 = mem_f[4u * wb2 + 3u];
            }
            if (ok1) __stcs(o4mem + k1, make_float4(pw1, v1.x, v1.y, v1.z));
            if (ok2) __stcs(o4mem + k2, make_float4(pw2, v2.x, v2.y, v2.z));
        }

        // Idle window: re-establish memory's lines in L2 for the dist pass.
        {
            const char* basep = (const char*)mem_f;
            unsigned bgt = (unsigned)(blockIdx.x - B_STATS) * NT + tid;   // 0..75775
            for (unsigned ln = bgt; ln < MEM_LINES; ln += (unsigned)B_COPY * NT)
                prefetch_l2(basep + (size_t)ln * 256u);
        }
    }

    // =================== everyone: wait for enc, then dist =================
    if (tid == 0) {
        while (*(volatile unsigned*)&g_encdone < (unsigned)CODE_LEN) __nanosleep(32);
    }
    __syncthreads();
    __threadfence();   // acquire g_enc

    {
        const int sub = lane & 7;
        const int g   = lane >> 3;
        const int w   = blockIdx.x * 8 + wid;          // 0..7103
        const float4* enc4 = (const float4*)g_enc;
        float4 e0 = enc4[sub];
        float4 e1 = enc4[sub + 8];
        float4 e2 = enc4[sub + 16];
        float4 e3 = enc4[sub + 24];

        float best = CUDART_INF_F;
        for (int q = w; q < NQUAD; q += NWARP_ALL) {
            unsigned base = (unsigned)(4 * q + g) * 32u + (unsigned)sub;
            float4 v0 = mem4[base];
            float4 v1 = mem4[base + 8u];
            float4 v2 = mem4[base + 16u];
            float4 v3 = mem4[base + 24u];
            float p = fabsf(v0.x - e0.x) + fabsf(v0.y - e0.y) + fabsf(v0.z - e0.z) + fabsf(v0.w - e0.w)
                    + fabsf(v1.x - e1.x) + fabsf(v1.y - e1.y) + fabsf(v1.z - e1.z) + fabsf(v1.w - e1.w)
                    + fabsf(v2.x - e2.x) + fabsf(v2.y - e2.y) + fabsf(v2.z - e2.z) + fabsf(v2.w - e2.w)
                    + fabsf(v3.x - e3.x) + fabsf(v3.y - e3.y) + fabsf(v3.z - e3.z) + fabsf(v3.w - e3.w);
            p += __shfl_xor_sync(FULL, p, 1);
            p += __shfl_xor_sync(FULL, p, 2);
            p += __shfl_xor_sync(FULL, p, 4);
            float m = fminf(p, __shfl_xor_sync(FULL, p, 8));
            m = fminf(m, __shfl_xor_sync(FULL, m, 16));
            best = fminf(best, m);
        }
        // block-level min staging: ONE global atomic per block
        __shared__ float smin[8];
        if (lane == 0) smin[wid] = best;
        __syncthreads();
        if (tid == 0) {
            float mm = smin[0];
            #pragma unroll
            for (int j = 1; j < 8; j++) mm = fminf(mm, smin[j]);
            atomicMin(&g_minbits, __float_as_int(mm));
        }
    }

    // =================== last-block final + re-arm =========================
    __threadfence();
    __syncthreads();
    __shared__ int s_last;
    if (tid == 0) s_last = (atomicAdd(&g_ticket, 1) == GRID - 1) ? 1 : 0;
    __syncthreads();
    if (s_last) {
        float loss = __int_as_float(atomicAdd(&g_minbits, 0));
        unsigned long long am = atomicAdd(&g_argmin, 0ULL);
        long long pos = (long long)(unsigned)(am & 0xFFFFFFFFULL);
        if (tid == 0) out[0] = loss;
        if (loss <= 1.0f) {
            if (tid < CODE_LEN) out[OUT_MEM_OFF + pos * CODE_LEN + tid] = g_enc[tid];
            out[OUT_MD_OFF + pos * IN_DIM + tid] = x[tid];
            if (tid == 0) out[OUT_IDX_OFF + pos] = (float)count[0];
        }
        __syncthreads();                 // done reading accumulators
        g_colsum[tid] = 0.0f;            // re-arm for next graph replay
        g_colsq[tid]  = 0.0f;
        if (tid == 0) {
            g_minbits = 0x7f800000;
            g_argmin  = 0xFFFFFFFFFFFFFFFFULL;
            g_ticket  = 0;
            g_sdone   = 0;
            g_encdone = 0;
        }
    }
}

// ---------------------------------------------------------------------------
extern "C" void kernel_launch(void* const* d_in, const int* in_sizes, int n_in,
                              void* d_out, int out_size) {
    const float* x        = (const float*)d_in[0];
    const float* memory   = (const float*)d_in[1];
    const float* mem_data = (const float*)d_in[2];
    const int*   mem_idx  = (const int*)d_in[3];
    const float* W        = (const float*)d_in[4];
    const float* b        = (const float*)d_in[5];
    const int*   count    = (const int*)d_in[6];
    float* out = (float*)d_out;

    fused<<<GRID, NT>>>(mem_data, out + OUT_MD_OFF,
                        memory,   out + OUT_MEM_OFF,
                        mem_idx,  out + OUT_IDX_OFF,
                        x, W, b, count, out);
}